// round 1
// baseline (speedup 1.0000x reference)
#include <cuda_runtime.h>
#include <cstdint>

#define NN 100000
#define NE 3200000
#define HID 64
#define NTILES (NN / 16)   // 6250, exact

// ---------------- scratch (device globals; no allocation) ----------------
__device__ float  g_deg[NN];
__device__ float  g_dinv[NN];
__device__ float2 g_xa[NN];          // 2-dim aggregated input (layer 1)
__device__ float  g_norm[NE];        // dinv[src]*dinv[dst] per edge
__device__ int    g_src[NE];
__device__ int    g_dst[NE];
__device__ float  g_h1[NN * HID];    // relu(layer-1 output)           25.6 MB
__device__ float  g_agg[NN * HID];   // layer-2 aggregation buffer     25.6 MB
__device__ float  g_pool[HID];
__device__ int    g_flag;            // 1 = edge_index stored as int64

// ---------------- vector RED helpers (sm_90+) ----------------
__device__ __forceinline__ void red_add_v2(float2* p, float a, float b) {
    asm volatile("red.global.add.v2.f32 [%0], {%1, %2};"
                 :: "l"(p), "f"(a), "f"(b) : "memory");
}
__device__ __forceinline__ void red_add_v4(float4* p, float4 v) {
    asm volatile("red.global.add.v4.f32 [%0], {%1, %2, %3, %4};"
                 :: "l"(p), "f"(v.x), "f"(v.y), "f"(v.z), "f"(v.w) : "memory");
}

// ---------------- kernels ----------------

// Detect whether edge_index is int64 or int32 (JAX may silently downcast).
__global__ void k_detect(const unsigned long long* __restrict__ e64) {
    int is64 = 1;
    #pragma unroll
    for (int i = 0; i < 8; i++) {
        if (e64[i] >= (unsigned long long)NN) { is64 = 0; break; }
    }
    g_flag = is64;
}

// Convert indices into clean int32 src/dst arrays.
__global__ void k_convert(const void* __restrict__ edges) {
    int e = blockIdx.x * blockDim.x + threadIdx.x;
    if (e >= NE) return;
    if (g_flag) {
        const long long* p = (const long long*)edges;
        g_src[e] = (int)p[e];
        g_dst[e] = (int)p[NE + e];
    } else {
        const int* p = (const int*)edges;
        g_src[e] = p[e];
        g_dst[e] = p[NE + e];
    }
}

// deg = 1 (self loop), zero pooled accumulator.
__global__ void k_init() {
    int i = blockIdx.x * blockDim.x + threadIdx.x;
    if (i < NN) g_deg[i] = 1.0f;
    if (i < HID) g_pool[i] = 0.0f;
}

// deg[dst] += 1 per edge.
__global__ void k_count() {
    int e = blockIdx.x * blockDim.x + threadIdx.x;
    if (e >= NE) return;
    atomicAdd(&g_deg[g_dst[e]], 1.0f);
}

// dinv = rsqrt(deg); xa init = x * dinv^2 (self-loop term, 2-dim space).
__global__ void k_dinv_xa(const float2* __restrict__ x2) {
    int i = blockIdx.x * blockDim.x + threadIdx.x;
    if (i >= NN) return;
    float d = rsqrtf(g_deg[i]);
    g_dinv[i] = d;
    float s = d * d;
    float2 xv = x2[i];
    g_xa[i] = make_float2(xv.x * s, xv.y * s);
}

// Layer-1 edge aggregation in 2-dim input space; also caches norm per edge.
__global__ void k_edge1(const float2* __restrict__ x2) {
    int e = blockIdx.x * blockDim.x + threadIdx.x;
    if (e >= NE) return;
    int s = g_src[e], d = g_dst[e];
    float nrm = g_dinv[s] * g_dinv[d];
    g_norm[e] = nrm;
    float2 xv = x2[s];
    red_add_v2(&g_xa[d], xv.x * nrm, xv.y * nrm);
}

// h1 = relu(xa @ W1 + b1); agg init = h1 * dinv^2 (layer-2 self loop).
__global__ void k_h1(const float* __restrict__ W1, const float* __restrict__ b1) {
    int gid = blockIdx.x * blockDim.x + threadIdx.x;
    if (gid >= NN * HID) return;
    int n = gid >> 6, f = gid & 63;
    float2 xa = g_xa[n];
    float v = fmaf(xa.x, W1[f], fmaf(xa.y, W1[HID + f], b1[f]));
    v = fmaxf(v, 0.0f);
    float d = g_dinv[n];
    g_h1[gid]  = v;
    g_agg[gid] = v * (d * d);
}

// Layer-2 edge aggregation of h1 (64-dim), one float4 chunk per thread,
// vector RED into agg[dst].
__global__ void k_edge2() {
    int gid = blockIdx.x * blockDim.x + threadIdx.x;   // NE*16 = 51.2M < 2^31
    if (gid >= NE * 16) return;
    int e = gid >> 4, c = gid & 15;
    int s = g_src[e], d = g_dst[e];
    float nrm = g_norm[e];
    const float4* h1v = (const float4*)g_h1;
    float4 v = h1v[s * 16 + c];
    v.x *= nrm; v.y *= nrm; v.z *= nrm; v.w *= nrm;
    red_add_v4(&((float4*)g_agg)[d * 16 + c], v);
}

// h2 = relu(agg @ W2 + b2), fused mean-pool column sums. h2 never hits gmem.
__global__ void __launch_bounds__(256) k_h2pool(const float* __restrict__ W2,
                                                const float* __restrict__ b2) {
    __shared__ float4 W2s[HID * 16];   // [k][fgrp] : W2 row-major as float4
    __shared__ float4 hs[16 * 16];     // 16 node rows x 16 float4
    __shared__ float  pool_s[HID];

    int tid = threadIdx.x;
    int fg  = tid & 15;                // feature group (4 features)
    int row = tid >> 4;                // node within tile

    if (tid < HID) pool_s[tid] = 0.0f;
    const float4* W2v = (const float4*)W2;
    #pragma unroll
    for (int i = 0; i < 4; i++) W2s[tid + i * 256] = W2v[tid + i * 256];
    float4 bb = ((const float4*)b2)[fg];
    __syncthreads();

    const float4* aggv = (const float4*)g_agg;
    for (int tile = blockIdx.x; tile < NTILES; tile += gridDim.x) {
        hs[tid] = aggv[tile * 256 + tid];
        __syncthreads();

        float4 acc = bb;
        const float4* hrow = &hs[row * 16];
        #pragma unroll
        for (int k4 = 0; k4 < 16; k4++) {
            float4 h4 = hrow[k4];
            float4 w0 = W2s[(k4 * 4 + 0) * 16 + fg];
            float4 w1 = W2s[(k4 * 4 + 1) * 16 + fg];
            float4 w2 = W2s[(k4 * 4 + 2) * 16 + fg];
            float4 w3 = W2s[(k4 * 4 + 3) * 16 + fg];
            acc.x = fmaf(h4.x, w0.x, acc.x); acc.y = fmaf(h4.x, w0.y, acc.y);
            acc.z = fmaf(h4.x, w0.z, acc.z); acc.w = fmaf(h4.x, w0.w, acc.w);
            acc.x = fmaf(h4.y, w1.x, acc.x); acc.y = fmaf(h4.y, w1.y, acc.y);
            acc.z = fmaf(h4.y, w1.z, acc.z); acc.w = fmaf(h4.y, w1.w, acc.w);
            acc.x = fmaf(h4.z, w2.x, acc.x); acc.y = fmaf(h4.z, w2.y, acc.y);
            acc.z = fmaf(h4.z, w2.z, acc.z); acc.w = fmaf(h4.z, w2.w, acc.w);
            acc.x = fmaf(h4.w, w3.x, acc.x); acc.y = fmaf(h4.w, w3.y, acc.y);
            acc.z = fmaf(h4.w, w3.z, acc.z); acc.w = fmaf(h4.w, w3.w, acc.w);
        }
        acc.x = fmaxf(acc.x, 0.0f); acc.y = fmaxf(acc.y, 0.0f);
        acc.z = fmaxf(acc.z, 0.0f); acc.w = fmaxf(acc.w, 0.0f);

        __syncthreads();
        hs[tid] = acc;                 // tid == row*16+fg
        __syncthreads();
        // tree-reduce across node rows
        for (int s2 = 8; s2 > 0; s2 >>= 1) {
            if (row < s2) {
                float4 o = hs[(row + s2) * 16 + fg];
                float4 m = hs[tid];
                m.x += o.x; m.y += o.y; m.z += o.z; m.w += o.w;
                hs[tid] = m;
            }
            __syncthreads();
        }
        if (row == 0) {
            float4 p = hs[fg];
            pool_s[4 * fg + 0] += p.x; pool_s[4 * fg + 1] += p.y;
            pool_s[4 * fg + 2] += p.z; pool_s[4 * fg + 3] += p.w;
        }
        __syncthreads();
    }
    if (tid < HID) atomicAdd(&g_pool[tid], pool_s[tid]);
}

// out = (pooled/N) @ Wfc + bfc   (OUT_DIM = 1)
__global__ void k_out(const float* __restrict__ Wfc, const float* __restrict__ bfc,
                      float* __restrict__ out) {
    int t = threadIdx.x;   // 32 threads
    float s = g_pool[t] * Wfc[t] + g_pool[t + 32] * Wfc[t + 32];
    #pragma unroll
    for (int o = 16; o > 0; o >>= 1) s += __shfl_down_sync(0xffffffffu, s, o);
    if (t == 0) out[0] = s * (1.0f / NN) + bfc[0];
}

// ---------------- launch ----------------
extern "C" void kernel_launch(void* const* d_in, const int* in_sizes, int n_in,
                              void* d_out, int out_size) {
    const float2* x2   = (const float2*)d_in[0];
    const void*   edges = d_in[1];
    const float*  W1   = (const float*)d_in[2];
    const float*  b1   = (const float*)d_in[3];
    const float*  W2   = (const float*)d_in[4];
    const float*  b2   = (const float*)d_in[5];
    const float*  Wfc  = (const float*)d_in[6];
    const float*  bfc  = (const float*)d_in[7];
    float* out = (float*)d_out;

    const int T = 256;
    k_detect<<<1, 1>>>((const unsigned long long*)edges);
    k_convert<<<(NE + T - 1) / T, T>>>(edges);
    k_init<<<(NN + T - 1) / T, T>>>();
    k_count<<<(NE + T - 1) / T, T>>>();
    k_dinv_xa<<<(NN + T - 1) / T, T>>>(x2);
    k_edge1<<<(NE + T - 1) / T, T>>>(x2);
    k_h1<<<(NN * HID + T - 1) / T, T>>>(W1, b1);
    k_edge2<<<(NE * 16 + T - 1) / T, T>>>();
    k_h2pool<<<1184, T>>>(W2, b2);
    k_out<<<1, 32>>>(Wfc, bfc, out);
}

// round 3
// speedup vs baseline: 1.5090x; 1.5090x over previous
#include <cuda_runtime.h>
#include <cuda_fp16.h>
#include <cstdint>

#define NN 100000
#define NE 3200000
#define HID 64
#define NTILES (NN / 16)          // 6250 exact
#define SCAN_B 512
#define NBLK1 ((NN + SCAN_B - 1) / SCAN_B)   // 196

// ---------------- scratch (device globals; no allocation) ----------------
__device__ int    g_cnt[NN];          // incoming-edge count
__device__ float  g_dinv[NN];
__device__ float2 g_xa[NN];           // layer-1 aggregate in 2-dim input space
__device__ int    g_src[NE];
__device__ int    g_dst[NE];
__device__ int    g_row[NN + 1];      // CSR row pointers (by dst)
__device__ int    g_cursor[NN];
__device__ int    g_sorted[NE];       // src ids sorted by dst
__device__ uint2  g_ph[NN * 16];      // p = dinv*relu(h1), fp16: 4 feats per uint2
__device__ float  g_pool[HID];
__device__ int    g_bsum[NBLK1];
__device__ int    g_flag;             // 1 = edge_index stored as int64

__device__ __forceinline__ void red_add_v2(float2* p, float a, float b) {
    asm volatile("red.global.add.v2.f32 [%0], {%1, %2};"
                 :: "l"(p), "f"(a), "f"(b) : "memory");
}

// ---------------- kernels ----------------

__global__ void k_detect(const unsigned long long* __restrict__ e64) {
    int is64 = 1;
    #pragma unroll
    for (int i = 0; i < 8; i++)
        if (e64[i] >= (unsigned long long)NN) { is64 = 0; break; }
    g_flag = is64;
}

__global__ void k_init() {
    int i = blockIdx.x * blockDim.x + threadIdx.x;
    if (i < NN) g_cnt[i] = 0;
    if (i < HID) g_pool[i] = 0.0f;
}

// Convert indices to int32 AND histogram dst in one pass.
__global__ void k_convert_count(const void* __restrict__ edges) {
    int e = blockIdx.x * blockDim.x + threadIdx.x;
    if (e >= NE) return;
    int s, d;
    if (g_flag) {
        const long long* p = (const long long*)edges;
        s = (int)p[e]; d = (int)p[NE + e];
    } else {
        const int* p = (const int*)edges;
        s = p[e]; d = p[NE + e];
    }
    g_src[e] = s;
    g_dst[e] = d;
    atomicAdd(&g_cnt[d], 1);
}

// --- 3-phase exclusive scan of g_cnt -> g_row ---
__global__ void k_scan1() {
    __shared__ int sh[SCAN_B];
    int t = threadIdx.x, i = blockIdx.x * SCAN_B + t;
    int v = (i < NN) ? g_cnt[i] : 0;
    sh[t] = v; __syncthreads();
    for (int off = 1; off < SCAN_B; off <<= 1) {
        int add = (t >= off) ? sh[t - off] : 0;
        __syncthreads();
        sh[t] += add;
        __syncthreads();
    }
    if (i < NN) g_row[i] = sh[t] - v;        // exclusive
    if (t == SCAN_B - 1) g_bsum[blockIdx.x] = sh[t];
}
__global__ void k_scan2() {
    __shared__ int sh[256];
    int t = threadIdx.x;
    int v = (t < NBLK1) ? g_bsum[t] : 0;
    sh[t] = v; __syncthreads();
    for (int off = 1; off < 256; off <<= 1) {
        int add = (t >= off) ? sh[t - off] : 0;
        __syncthreads();
        sh[t] += add;
        __syncthreads();
    }
    if (t < NBLK1) g_bsum[t] = sh[t] - v;    // exclusive block offsets
}
__global__ void k_scan3() {
    int i = blockIdx.x * blockDim.x + threadIdx.x;
    if (i < NN) {
        int r = g_row[i] + g_bsum[i / SCAN_B];
        g_row[i] = r;
        g_cursor[i] = r;
    }
    if (i == 0) g_row[NN] = NE;
}

// dinv = rsqrt(cnt+1); xa self-loop init.
__global__ void k_dinv(const float2* __restrict__ x2) {
    int i = blockIdx.x * blockDim.x + threadIdx.x;
    if (i >= NN) return;
    float d = rsqrtf((float)g_cnt[i] + 1.0f);
    g_dinv[i] = d;
    float s = d * d;
    float2 xv = x2[i];
    g_xa[i] = make_float2(xv.x * s, xv.y * s);
}

// Build sorted-by-dst src list; fused layer-1 edge aggregation (2-dim, RED v2).
__global__ void k_scatter(const float2* __restrict__ x2) {
    int e = blockIdx.x * blockDim.x + threadIdx.x;
    if (e >= NE) return;
    int s = g_src[e], d = g_dst[e];
    int pos = atomicAdd(&g_cursor[d], 1);
    g_sorted[pos] = s;
    float nrm = g_dinv[s] * g_dinv[d];
    float2 xv = __ldg(&x2[s]);
    red_add_v2(&g_xa[d], xv.x * nrm, xv.y * nrm);
}

// p = dinv * relu(xa @ W1 + b1) stored fp16. Two features per thread.
__global__ void k_h1p(const float* __restrict__ W1, const float* __restrict__ b1) {
    int gid = blockIdx.x * blockDim.x + threadIdx.x;   // NN*32
    if (gid >= NN * 32) return;
    int n = gid >> 5, j = gid & 31;                    // features 2j, 2j+1
    float2 xa = g_xa[n];
    float dv = g_dinv[n];
    int f0 = 2 * j;
    float v0 = fmaf(xa.x, W1[f0],     fmaf(xa.y, W1[HID + f0],     b1[f0]));
    float v1 = fmaf(xa.x, W1[f0 + 1], fmaf(xa.y, W1[HID + f0 + 1], b1[f0 + 1]));
    v0 = fmaxf(v0, 0.0f) * dv;
    v1 = fmaxf(v1, 0.0f) * dv;
    ((__half2*)g_ph)[gid] = __floats2half2_rn(v0, v1);
}

__device__ __forceinline__ void acc_uint2(float4& acc, uint2 r) {
    float2 fa = __half22float2(*(__half2*)&r.x);
    float2 fb = __half22float2(*(__half2*)&r.y);
    acc.x += fa.x; acc.y += fa.y; acc.z += fb.x; acc.w += fb.y;
}

// Fused: CSR gather of p (layer-2 aggregation) + h2 GEMV + relu + mean-pool.
// 16 threads per node (4 features each), 16 nodes per block.
__global__ void __launch_bounds__(256) k_gather2(const float* __restrict__ W2,
                                                 const float* __restrict__ b2) {
    __shared__ float4 W2s[HID * 16];
    __shared__ float4 hs[16 * 16];
    __shared__ float  pool_s[HID];

    int tid = threadIdx.x;
    int fg  = tid & 15;       // feature group (4 feats)
    int row = tid >> 4;       // node within tile

    if (tid < HID) pool_s[tid] = 0.0f;
    const float4* W2v = (const float4*)W2;
    #pragma unroll
    for (int i = 0; i < 4; i++) W2s[tid + i * 256] = W2v[tid + i * 256];
    float4 bb = ((const float4*)b2)[fg];
    __syncthreads();

    for (int tile = blockIdx.x; tile < NTILES; tile += gridDim.x) {
        int n = tile * 16 + row;
        int e0 = g_row[n], e1 = g_row[n + 1];
        float4 acc = make_float4(0.f, 0.f, 0.f, 0.f);

        int e = e0;
        for (; e + 4 <= e1; e += 4) {
            int s0 = __ldg(&g_sorted[e]),     s1 = __ldg(&g_sorted[e + 1]);
            int s2 = __ldg(&g_sorted[e + 2]), s3 = __ldg(&g_sorted[e + 3]);
            uint2 r0 = __ldg(&g_ph[s0 * 16 + fg]);
            uint2 r1 = __ldg(&g_ph[s1 * 16 + fg]);
            uint2 r2 = __ldg(&g_ph[s2 * 16 + fg]);
            uint2 r3 = __ldg(&g_ph[s3 * 16 + fg]);
            acc_uint2(acc, r0); acc_uint2(acc, r1);
            acc_uint2(acc, r2); acc_uint2(acc, r3);
        }
        for (; e < e1; e++)
            acc_uint2(acc, __ldg(&g_ph[__ldg(&g_sorted[e]) * 16 + fg]));

        // self loop + normalization: agg = dinv[n] * (sum + p[n])
        acc_uint2(acc, g_ph[n * 16 + fg]);
        float dv = g_dinv[n];
        acc.x *= dv; acc.y *= dv; acc.z *= dv; acc.w *= dv;

        hs[tid] = acc;
        __syncthreads();

        // h2 = relu(agg @ W2 + b2) for this node's 4 output features
        float4 o = bb;
        const float4* hrow = &hs[row * 16];
        #pragma unroll
        for (int k4 = 0; k4 < 16; k4++) {
            float4 h4 = hrow[k4];
            float4 w0 = W2s[(k4 * 4 + 0) * 16 + fg];
            float4 w1 = W2s[(k4 * 4 + 1) * 16 + fg];
            float4 w2 = W2s[(k4 * 4 + 2) * 16 + fg];
            float4 w3 = W2s[(k4 * 4 + 3) * 16 + fg];
            o.x = fmaf(h4.x, w0.x, o.x); o.y = fmaf(h4.x, w0.y, o.y);
            o.z = fmaf(h4.x, w0.z, o.z); o.w = fmaf(h4.x, w0.w, o.w);
            o.x = fmaf(h4.y, w1.x, o.x); o.y = fmaf(h4.y, w1.y, o.y);
            o.z = fmaf(h4.y, w1.z, o.z); o.w = fmaf(h4.y, w1.w, o.w);
            o.x = fmaf(h4.z, w2.x, o.x); o.y = fmaf(h4.z, w2.y, o.y);
            o.z = fmaf(h4.z, w2.z, o.z); o.w = fmaf(h4.z, w2.w, o.w);
            o.x = fmaf(h4.w, w3.x, o.x); o.y = fmaf(h4.w, w3.y, o.y);
            o.z = fmaf(h4.w, w3.z, o.z); o.w = fmaf(h4.w, w3.w, o.w);
        }
        o.x = fmaxf(o.x, 0.f); o.y = fmaxf(o.y, 0.f);
        o.z = fmaxf(o.z, 0.f); o.w = fmaxf(o.w, 0.f);

        __syncthreads();
        hs[tid] = o;
        __syncthreads();
        for (int s2 = 8; s2 > 0; s2 >>= 1) {
            if (row < s2) {
                float4 q = hs[(row + s2) * 16 + fg];
                float4 m = hs[tid];
                m.x += q.x; m.y += q.y; m.z += q.z; m.w += q.w;
                hs[tid] = m;
            }
            __syncthreads();
        }
        if (row == 0) {
            float4 p = hs[fg];
            pool_s[4 * fg + 0] += p.x; pool_s[4 * fg + 1] += p.y;
            pool_s[4 * fg + 2] += p.z; pool_s[4 * fg + 3] += p.w;
        }
        __syncthreads();
    }
    if (tid < HID) atomicAdd(&g_pool[tid], pool_s[tid]);
}

__global__ void k_out(const float* __restrict__ Wfc, const float* __restrict__ bfc,
                      float* __restrict__ out) {
    int t = threadIdx.x;   // 32 threads
    float s = g_pool[t] * Wfc[t] + g_pool[t + 32] * Wfc[t + 32];
    #pragma unroll
    for (int o = 16; o > 0; o >>= 1) s += __shfl_down_sync(0xffffffffu, s, o);
    if (t == 0) out[0] = s * (1.0f / NN) + bfc[0];
}

// ---------------- launch ----------------
extern "C" void kernel_launch(void* const* d_in, const int* in_sizes, int n_in,
                              void* d_out, int out_size) {
    const float2* x2    = (const float2*)d_in[0];
    const void*   edges = d_in[1];
    const float*  W1    = (const float*)d_in[2];
    const float*  b1    = (const float*)d_in[3];
    const float*  W2    = (const float*)d_in[4];
    const float*  b2    = (const float*)d_in[5];
    const float*  Wfc   = (const float*)d_in[6];
    const float*  bfc   = (const float*)d_in[7];
    float* out = (float*)d_out;

    const int T = 256;
    k_detect<<<1, 1>>>((const unsigned long long*)edges);
    k_init<<<(NN + T - 1) / T, T>>>();
    k_convert_count<<<(NE + T - 1) / T, T>>>(edges);
    k_scan1<<<NBLK1, SCAN_B>>>();
    k_scan2<<<1, 256>>>();
    k_scan3<<<(NN + T - 1) / T, T>>>();
    k_dinv<<<(NN + T - 1) / T, T>>>(x2);
    k_scatter<<<(NE + T - 1) / T, T>>>(x2);
    k_h1p<<<(NN * 32 + T - 1) / T, T>>>(W1, b1);
    k_gather2<<<1480, T>>>(W2, b2);
    k_out<<<1, 32>>>(Wfc, bfc, out);
}

// round 4
// speedup vs baseline: 1.6442x; 1.0896x over previous
#include <cuda_runtime.h>
#include <cuda_fp16.h>
#include <cstdint>

#define NN 100000
#define NE 3200000
#define HID 64
#define NTILES (NN / 16)          // 6250 exact
#define SCAN_B 512
#define NBLK1 ((NN + SCAN_B - 1) / SCAN_B)   // 196

// ---------------- scratch (device globals; no allocation) ----------------
__device__ int    g_cnt[NN];          // incoming-edge count
__device__ float  g_dinv[NN];
__device__ float2 g_q[NN];            // q = dinv * x  (layer-1 gather table)
__device__ int    g_row[NN + 1];      // CSR row pointers (by dst)
__device__ int    g_cursor[NN];
__device__ int    g_sorted[NE];       // src ids sorted by dst
__device__ uint2  g_ph[NN * 16];      // p = dinv*relu(h1), fp16: 4 feats per uint2
__device__ float  g_pool[HID];
__device__ int    g_bsum[NBLK1];
__device__ int    g_flag;             // 1 = edge_index stored as int64

// ---------------- kernels ----------------

__global__ void k_detect(const unsigned long long* __restrict__ e64) {
    int is64 = 1;
    #pragma unroll
    for (int i = 0; i < 8; i++)
        if (e64[i] >= (unsigned long long)NN) { is64 = 0; break; }
    g_flag = is64;
}

__global__ void k_init() {
    int i = blockIdx.x * blockDim.x + threadIdx.x;
    if (i < NN) g_cnt[i] = 0;
    if (i < HID) g_pool[i] = 0.0f;
}

// Histogram dst straight from the raw edge list. 4 edges per thread.
__global__ void k_count(const void* __restrict__ edges) {
    int e0 = (blockIdx.x * blockDim.x + threadIdx.x) * 4;
    if (e0 >= NE) return;
    if (g_flag) {
        const longlong2* d2 = (const longlong2*)((const long long*)edges + NE);
        longlong2 a = d2[e0 >> 1], b = d2[(e0 >> 1) + 1];
        atomicAdd(&g_cnt[(int)a.x], 1);
        atomicAdd(&g_cnt[(int)a.y], 1);
        atomicAdd(&g_cnt[(int)b.x], 1);
        atomicAdd(&g_cnt[(int)b.y], 1);
    } else {
        const int4* d4 = (const int4*)((const int*)edges + NE);
        int4 a = d4[e0 >> 2];
        atomicAdd(&g_cnt[a.x], 1);
        atomicAdd(&g_cnt[a.y], 1);
        atomicAdd(&g_cnt[a.z], 1);
        atomicAdd(&g_cnt[a.w], 1);
    }
}

// --- shfl-based exclusive scan of g_cnt -> g_row (partial) ---
__global__ void k_scan1() {
    __shared__ int wsum[16];
    int t = threadIdx.x, i = blockIdx.x * SCAN_B + t;
    int lane = t & 31, w = t >> 5;
    int v = (i < NN) ? g_cnt[i] : 0;
    int s = v;
    #pragma unroll
    for (int o = 1; o < 32; o <<= 1) {
        int u = __shfl_up_sync(0xffffffffu, s, o);
        if (lane >= o) s += u;
    }
    if (lane == 31) wsum[w] = s;
    __syncthreads();
    if (w == 0) {
        int ws = (lane < 16) ? wsum[lane] : 0;
        #pragma unroll
        for (int o = 1; o < 16; o <<= 1) {
            int u = __shfl_up_sync(0xffffffffu, ws, o);
            if (lane >= o) ws += u;
        }
        if (lane < 16) wsum[lane] = ws;
    }
    __syncthreads();
    int base = (w > 0) ? wsum[w - 1] : 0;
    int incl = s + base;
    if (i < NN) g_row[i] = incl - v;          // exclusive
    if (t == SCAN_B - 1) g_bsum[blockIdx.x] = incl;
}

__global__ void k_scan2() {
    __shared__ int wsum[8];
    int t = threadIdx.x;                       // 256 threads
    int lane = t & 31, w = t >> 5;
    int v = (t < NBLK1) ? g_bsum[t] : 0;
    int s = v;
    #pragma unroll
    for (int o = 1; o < 32; o <<= 1) {
        int u = __shfl_up_sync(0xffffffffu, s, o);
        if (lane >= o) s += u;
    }
    if (lane == 31) wsum[w] = s;
    __syncthreads();
    if (w == 0) {
        int ws = (lane < 8) ? wsum[lane] : 0;
        #pragma unroll
        for (int o = 1; o < 8; o <<= 1) {
            int u = __shfl_up_sync(0xffffffffu, ws, o);
            if (lane >= o) ws += u;
        }
        if (lane < 8) wsum[lane] = ws;
    }
    __syncthreads();
    int base = (w > 0) ? wsum[w - 1] : 0;
    if (t < NBLK1) g_bsum[t] = s + base - v;   // exclusive block offsets
}

// Finalize row pointers; cursor init; dinv; q = dinv*x.
__global__ void k_scan3_dinv(const float2* __restrict__ x2) {
    int i = blockIdx.x * blockDim.x + threadIdx.x;
    if (i < NN) {
        int r = g_row[i] + g_bsum[i / SCAN_B];
        g_row[i] = r;
        g_cursor[i] = r;
        float d = rsqrtf((float)g_cnt[i] + 1.0f);
        g_dinv[i] = d;
        float2 xv = x2[i];
        g_q[i] = make_float2(xv.x * d, xv.y * d);
    }
    if (i == 0) g_row[NN] = NE;
}

// Counting-sort scatter straight from raw edges. 2 edges per thread.
__global__ void k_scatter(const void* __restrict__ edges) {
    int e0 = (blockIdx.x * blockDim.x + threadIdx.x) * 2;
    if (e0 >= NE) return;
    int s0, s1, d0, d1;
    if (g_flag) {
        const longlong2* sp = (const longlong2*)edges;
        const longlong2* dp = (const longlong2*)((const long long*)edges + NE);
        longlong2 sv = sp[e0 >> 1], dv = dp[e0 >> 1];
        s0 = (int)sv.x; s1 = (int)sv.y; d0 = (int)dv.x; d1 = (int)dv.y;
    } else {
        const int2* sp = (const int2*)edges;
        const int2* dp = (const int2*)((const int*)edges + NE);
        int2 sv = sp[e0 >> 1], dv = dp[e0 >> 1];
        s0 = sv.x; s1 = sv.y; d0 = dv.x; d1 = dv.y;
    }
    int p0 = atomicAdd(&g_cursor[d0], 1);
    int p1 = atomicAdd(&g_cursor[d1], 1);
    g_sorted[p0] = s0;
    g_sorted[p1] = s1;
}

// Warp-per-node: layer-1 CSR gather of q + 2->64 GEMV + relu -> fp16 p row.
__global__ void __launch_bounds__(256) k_h1p(const float* __restrict__ W1,
                                             const float* __restrict__ b1) {
    int gt = blockIdx.x * blockDim.x + threadIdx.x;
    int n = gt >> 5;
    if (n >= NN) return;
    int lane = gt & 31;

    int e0 = g_row[n], e1 = g_row[n + 1];
    float ax = 0.f, ay = 0.f;
    for (int e = e0 + lane; e < e1; e += 32) {
        float2 q = __ldg(&g_q[g_sorted[e]]);
        ax += q.x; ay += q.y;
    }
    #pragma unroll
    for (int o = 16; o > 0; o >>= 1) {
        ax += __shfl_xor_sync(0xffffffffu, ax, o);
        ay += __shfl_xor_sync(0xffffffffu, ay, o);
    }
    float2 qn = g_q[n];
    float dv = g_dinv[n];
    float xax = (ax + qn.x) * dv;
    float xay = (ay + qn.y) * dv;

    int f = 2 * lane;
    float v0 = fmaf(xax, __ldg(&W1[f]),     fmaf(xay, __ldg(&W1[HID + f]),     __ldg(&b1[f])));
    float v1 = fmaf(xax, __ldg(&W1[f + 1]), fmaf(xay, __ldg(&W1[HID + f + 1]), __ldg(&b1[f + 1])));
    v0 = fmaxf(v0, 0.0f) * dv;
    v1 = fmaxf(v1, 0.0f) * dv;
    ((__half2*)g_ph)[n * 32 + lane] = __floats2half2_rn(v0, v1);
}

__device__ __forceinline__ void acc_uint2(float4& acc, uint2 r) {
    float2 fa = __half22float2(*(__half2*)&r.x);
    float2 fb = __half22float2(*(__half2*)&r.y);
    acc.x += fa.x; acc.y += fa.y; acc.z += fb.x; acc.w += fb.y;
}

// Fused: CSR gather of p (layer-2 aggregation) + h2 GEMV + relu + mean-pool.
__global__ void __launch_bounds__(256) k_gather2(const float* __restrict__ W2,
                                                 const float* __restrict__ b2) {
    __shared__ float4 W2s[HID * 16];
    __shared__ float4 hs[16 * 16];
    __shared__ float  pool_s[HID];

    int tid = threadIdx.x;
    int fg  = tid & 15;       // feature group (4 feats)
    int row = tid >> 4;       // node within tile

    if (tid < HID) pool_s[tid] = 0.0f;
    const float4* W2v = (const float4*)W2;
    #pragma unroll
    for (int i = 0; i < 4; i++) W2s[tid + i * 256] = W2v[tid + i * 256];
    float4 bb = ((const float4*)b2)[fg];
    __syncthreads();

    for (int tile = blockIdx.x; tile < NTILES; tile += gridDim.x) {
        int n = tile * 16 + row;
        int e0 = g_row[n], e1 = g_row[n + 1];
        float4 acc = make_float4(0.f, 0.f, 0.f, 0.f);

        int e = e0;
        for (; e + 4 <= e1; e += 4) {
            int s0 = __ldg(&g_sorted[e]),     s1 = __ldg(&g_sorted[e + 1]);
            int s2 = __ldg(&g_sorted[e + 2]), s3 = __ldg(&g_sorted[e + 3]);
            uint2 r0 = __ldg(&g_ph[s0 * 16 + fg]);
            uint2 r1 = __ldg(&g_ph[s1 * 16 + fg]);
            uint2 r2 = __ldg(&g_ph[s2 * 16 + fg]);
            uint2 r3 = __ldg(&g_ph[s3 * 16 + fg]);
            acc_uint2(acc, r0); acc_uint2(acc, r1);
            acc_uint2(acc, r2); acc_uint2(acc, r3);
        }
        for (; e < e1; e++)
            acc_uint2(acc, __ldg(&g_ph[__ldg(&g_sorted[e]) * 16 + fg]));

        // self loop + normalization: agg = dinv[n] * (sum + p[n])
        acc_uint2(acc, g_ph[n * 16 + fg]);
        float dv = g_dinv[n];
        acc.x *= dv; acc.y *= dv; acc.z *= dv; acc.w *= dv;

        hs[tid] = acc;
        __syncthreads();

        float4 o = bb;
        const float4* hrow = &hs[row * 16];
        #pragma unroll
        for (int k4 = 0; k4 < 16; k4++) {
            float4 h4 = hrow[k4];
            float4 w0 = W2s[(k4 * 4 + 0) * 16 + fg];
            float4 w1 = W2s[(k4 * 4 + 1) * 16 + fg];
            float4 w2 = W2s[(k4 * 4 + 2) * 16 + fg];
            float4 w3 = W2s[(k4 * 4 + 3) * 16 + fg];
            o.x = fmaf(h4.x, w0.x, o.x); o.y = fmaf(h4.x, w0.y, o.y);
            o.z = fmaf(h4.x, w0.z, o.z); o.w = fmaf(h4.x, w0.w, o.w);
            o.x = fmaf(h4.y, w1.x, o.x); o.y = fmaf(h4.y, w1.y, o.y);
            o.z = fmaf(h4.y, w1.z, o.z); o.w = fmaf(h4.y, w1.w, o.w);
            o.x = fmaf(h4.z, w2.x, o.x); o.y = fmaf(h4.z, w2.y, o.y);
            o.z = fmaf(h4.z, w2.z, o.z); o.w = fmaf(h4.z, w2.w, o.w);
            o.x = fmaf(h4.w, w3.x, o.x); o.y = fmaf(h4.w, w3.y, o.y);
            o.z = fmaf(h4.w, w3.z, o.z); o.w = fmaf(h4.w, w3.w, o.w);
        }
        o.x = fmaxf(o.x, 0.f); o.y = fmaxf(o.y, 0.f);
        o.z = fmaxf(o.z, 0.f); o.w = fmaxf(o.w, 0.f);

        __syncthreads();
        hs[tid] = o;
        __syncthreads();
        for (int s2 = 8; s2 > 0; s2 >>= 1) {
            if (row < s2) {
                float4 qv = hs[(row + s2) * 16 + fg];
                float4 m = hs[tid];
                m.x += qv.x; m.y += qv.y; m.z += qv.z; m.w += qv.w;
                hs[tid] = m;
            }
            __syncthreads();
        }
        if (row == 0) {
            float4 p = hs[fg];
            pool_s[4 * fg + 0] += p.x; pool_s[4 * fg + 1] += p.y;
            pool_s[4 * fg + 2] += p.z; pool_s[4 * fg + 3] += p.w;
        }
        __syncthreads();
    }
    if (tid < HID) atomicAdd(&g_pool[tid], pool_s[tid]);
}

__global__ void k_out(const float* __restrict__ Wfc, const float* __restrict__ bfc,
                      float* __restrict__ out) {
    int t = threadIdx.x;   // 32 threads
    float s = g_pool[t] * Wfc[t] + g_pool[t + 32] * Wfc[t + 32];
    #pragma unroll
    for (int o = 16; o > 0; o >>= 1) s += __shfl_down_sync(0xffffffffu, s, o);
    if (t == 0) out[0] = s * (1.0f / NN) + bfc[0];
}

// ---------------- launch ----------------
extern "C" void kernel_launch(void* const* d_in, const int* in_sizes, int n_in,
                              void* d_out, int out_size) {
    const float2* x2    = (const float2*)d_in[0];
    const void*   edges = d_in[1];
    const float*  W1    = (const float*)d_in[2];
    const float*  b1    = (const float*)d_in[3];
    const float*  W2    = (const float*)d_in[4];
    const float*  b2    = (const float*)d_in[5];
    const float*  Wfc   = (const float*)d_in[6];
    const float*  bfc   = (const float*)d_in[7];
    float* out = (float*)d_out;

    const int T = 256;
    k_detect<<<1, 1>>>((const unsigned long long*)edges);
    k_init<<<(NN + T - 1) / T, T>>>();
    k_count<<<(NE / 4 + T - 1) / T, T>>>(edges);
    k_scan1<<<NBLK1, SCAN_B>>>();
    k_scan2<<<1, 256>>>();
    k_scan3_dinv<<<(NN + T - 1) / T, T>>>(x2);
    k_scatter<<<(NE / 2 + T - 1) / T, T>>>(edges);
    k_h1p<<<(NN * 32 + T - 1) / T, T>>>(W1, b1);
    k_gather2<<<1480, T>>>(W2, b2);
    k_out<<<1, 32>>>(Wfc, bfc, out);
}

// round 6
// speedup vs baseline: 1.8864x; 1.1473x over previous
#include <cuda_runtime.h>
#include <cuda_fp16.h>
#include <cstdint>

#define NN 100000
#define NE 3200000
#define HID 64
#define SCAN_B 512
#define NBLK1 ((NN + SCAN_B - 1) / SCAN_B)   // 196
#define TILE2 128
#define NT2 ((NN + TILE2 - 1) / TILE2)       // 782
#define HS_STRIDE 66                          // halves; word idx = 33*row + k/2
#define P_SCALE 16.0f
#define P_INV   0.0625f

// ---------------- scratch (device globals; no allocation) ----------------
__device__ int    g_cnt[NN];
__device__ float  g_dinv[NN];
__device__ float2 g_q[NN];            // q = dinv * x (layer-1 gather table)
__device__ int    g_row[NN + 1];      // CSR row pointers (by dst)
__device__ int    g_cursor[NN];
__device__ int    g_sorted[NE];       // src ids sorted by dst
__device__ unsigned short g_p8[NN * 32];  // 64 e4m3 per node (16*p), 64 B/row
__device__ float  g_pool[HID];
__device__ int    g_bsum[NBLK1];
__device__ int    g_flag;             // 1 = edge_index stored as int64

// e4m3x2 (packed in ushort) -> half2
__device__ __forceinline__ __half2 cvt8(unsigned short u) {
    unsigned int r;
    asm("cvt.rn.f16x2.e4m3x2 %0, %1;" : "=r"(r) : "h"(u));
    return *reinterpret_cast<__half2*>(&r);
}
// two floats -> packed e4m3x2 (lo byte = a)
__device__ __forceinline__ unsigned short cvt_to8(float a, float b) {
    unsigned short u;
    asm("cvt.rn.satfinite.e4m3x2.f32 %0, %1, %2;" : "=h"(u) : "f"(b), "f"(a));
    return u;
}

// ---------------- kernels ----------------

__global__ void k_detect(const unsigned long long* __restrict__ e64) {
    int is64 = 1;
    #pragma unroll
    for (int i = 0; i < 8; i++)
        if (e64[i] >= (unsigned long long)NN) { is64 = 0; break; }
    g_flag = is64;
}

__global__ void k_init() {
    int i = blockIdx.x * blockDim.x + threadIdx.x;
    if (i < NN) g_cnt[i] = 0;
    if (i < HID) g_pool[i] = 0.0f;
}

// Histogram dst straight from the raw edge list. 4 edges per thread.
__global__ void k_count(const void* __restrict__ edges) {
    int e0 = (blockIdx.x * blockDim.x + threadIdx.x) * 4;
    if (e0 >= NE) return;
    if (g_flag) {
        const longlong2* d2 = (const longlong2*)((const long long*)edges + NE);
        longlong2 a = d2[e0 >> 1], b = d2[(e0 >> 1) + 1];
        atomicAdd(&g_cnt[(int)a.x], 1);
        atomicAdd(&g_cnt[(int)a.y], 1);
        atomicAdd(&g_cnt[(int)b.x], 1);
        atomicAdd(&g_cnt[(int)b.y], 1);
    } else {
        const int4* d4 = (const int4*)((const int*)edges + NE);
        int4 a = d4[e0 >> 2];
        atomicAdd(&g_cnt[a.x], 1);
        atomicAdd(&g_cnt[a.y], 1);
        atomicAdd(&g_cnt[a.z], 1);
        atomicAdd(&g_cnt[a.w], 1);
    }
}

// --- shfl-based exclusive scan of g_cnt -> g_row ---
__global__ void k_scan1() {
    __shared__ int wsum[16];
    int t = threadIdx.x, i = blockIdx.x * SCAN_B + t;
    int lane = t & 31, w = t >> 5;
    int v = (i < NN) ? g_cnt[i] : 0;
    int s = v;
    #pragma unroll
    for (int o = 1; o < 32; o <<= 1) {
        int u = __shfl_up_sync(0xffffffffu, s, o);
        if (lane >= o) s += u;
    }
    if (lane == 31) wsum[w] = s;
    __syncthreads();
    if (w == 0) {
        int ws = (lane < 16) ? wsum[lane] : 0;
        #pragma unroll
        for (int o = 1; o < 16; o <<= 1) {
            int u = __shfl_up_sync(0xffffffffu, ws, o);
            if (lane >= o) ws += u;
        }
        if (lane < 16) wsum[lane] = ws;
    }
    __syncthreads();
    int base = (w > 0) ? wsum[w - 1] : 0;
    int incl = s + base;
    if (i < NN) g_row[i] = incl - v;
    if (t == SCAN_B - 1) g_bsum[blockIdx.x] = incl;
}

__global__ void k_scan2() {
    __shared__ int wsum[8];
    int t = threadIdx.x;
    int lane = t & 31, w = t >> 5;
    int v = (t < NBLK1) ? g_bsum[t] : 0;
    int s = v;
    #pragma unroll
    for (int o = 1; o < 32; o <<= 1) {
        int u = __shfl_up_sync(0xffffffffu, s, o);
        if (lane >= o) s += u;
    }
    if (lane == 31) wsum[w] = s;
    __syncthreads();
    if (w == 0) {
        int ws = (lane < 8) ? wsum[lane] : 0;
        #pragma unroll
        for (int o = 1; o < 8; o <<= 1) {
            int u = __shfl_up_sync(0xffffffffu, ws, o);
            if (lane >= o) ws += u;
        }
        if (lane < 8) wsum[lane] = ws;
    }
    __syncthreads();
    int base = (w > 0) ? wsum[w - 1] : 0;
    if (t < NBLK1) g_bsum[t] = s + base - v;
}

__global__ void k_scan3_dinv(const float2* __restrict__ x2) {
    int i = blockIdx.x * blockDim.x + threadIdx.x;
    if (i < NN) {
        int r = g_row[i] + g_bsum[i / SCAN_B];
        g_row[i] = r;
        g_cursor[i] = r;
        float d = rsqrtf((float)g_cnt[i] + 1.0f);
        g_dinv[i] = d;
        float2 xv = x2[i];
        g_q[i] = make_float2(xv.x * d, xv.y * d);
    }
    if (i == 0) g_row[NN] = NE;
}

// Counting-sort scatter from raw edges. 2 edges per thread.
__global__ void k_scatter(const void* __restrict__ edges) {
    int e0 = (blockIdx.x * blockDim.x + threadIdx.x) * 2;
    if (e0 >= NE) return;
    int s0, s1, d0, d1;
    if (g_flag) {
        const longlong2* sp = (const longlong2*)edges;
        const longlong2* dp = (const longlong2*)((const long long*)edges + NE);
        longlong2 sv = sp[e0 >> 1], dv = dp[e0 >> 1];
        s0 = (int)sv.x; s1 = (int)sv.y; d0 = (int)dv.x; d1 = (int)dv.y;
    } else {
        const int2* sp = (const int2*)edges;
        const int2* dp = (const int2*)((const int*)edges + NE);
        int2 sv = sp[e0 >> 1], dv = dp[e0 >> 1];
        s0 = sv.x; s1 = sv.y; d0 = dv.x; d1 = dv.y;
    }
    int p0 = atomicAdd(&g_cursor[d0], 1);
    int p1 = atomicAdd(&g_cursor[d1], 1);
    g_sorted[p0] = s0;
    g_sorted[p1] = s1;
}

// Warp-per-node: layer-1 CSR gather of q + 2->64 GEMV + relu -> fp8 p row.
__global__ void __launch_bounds__(256) k_h1p(const float* __restrict__ W1,
                                             const float* __restrict__ b1) {
    int gt = blockIdx.x * blockDim.x + threadIdx.x;
    int n = gt >> 5;
    if (n >= NN) return;
    int lane = gt & 31;

    int e0 = g_row[n], e1 = g_row[n + 1];
    float ax = 0.f, ay = 0.f;
    for (int e = e0 + lane; e < e1; e += 32) {
        float2 q = __ldg(&g_q[g_sorted[e]]);
        ax += q.x; ay += q.y;
    }
    #pragma unroll
    for (int o = 16; o > 0; o >>= 1) {
        ax += __shfl_xor_sync(0xffffffffu, ax, o);
        ay += __shfl_xor_sync(0xffffffffu, ay, o);
    }
    float2 qn = g_q[n];
    float dv = g_dinv[n];
    float xax = (ax + qn.x) * dv;
    float xay = (ay + qn.y) * dv;

    int f = 2 * lane;
    float v0 = fmaf(xax, __ldg(&W1[f]),     fmaf(xay, __ldg(&W1[HID + f]),     __ldg(&b1[f])));
    float v1 = fmaf(xax, __ldg(&W1[f + 1]), fmaf(xay, __ldg(&W1[HID + f + 1]), __ldg(&b1[f + 1])));
    v0 = fmaxf(v0, 0.0f) * dv * P_SCALE;
    v1 = fmaxf(v1, 0.0f) * dv * P_SCALE;
    g_p8[n * 32 + lane] = cvt_to8(v0, v1);
}

// Fused: fp8 CSR gather (layer-2 agg) + node-batched h2 GEMV + relu + pool.
// 256 threads: fg = tid&7 (8 feats), rg = tid>>3; thread handles nodes rg*4+i.
// agg staged in fp16 (stride 66 halves -> conflict-free, 16.9 KB).
__global__ void __launch_bounds__(256) k_gather2(const float* __restrict__ W2,
                                                 const float* __restrict__ b2) {
    __shared__ float  W2s[HID * HID];             // 16 KB, [k*64 + f]
    __shared__ __half hs[TILE2 * HS_STRIDE];      // 16.9 KB

    int tid = threadIdx.x;
    int fg = tid & 7, rg = tid >> 3;

    for (int i = tid; i < HID * HID; i += 256) W2s[i] = W2[i];
    float bloc[8];
    #pragma unroll
    for (int j = 0; j < 8; j++) bloc[j] = __ldg(&b2[8 * fg + j]);
    __syncthreads();

    float pool8[8] = {0.f, 0.f, 0.f, 0.f, 0.f, 0.f, 0.f, 0.f};
    const ushort4* pt = (const ushort4*)g_p8;

    for (int tile = blockIdx.x; tile < NT2; tile += gridDim.x) {
        // -------- stage A: gather agg for 4 nodes, write fp16 to hs --------
        #pragma unroll
        for (int i = 0; i < 4; i++) {
            int nl = rg * 4 + i;
            int n = tile * TILE2 + nl;
            float acc[8] = {0.f, 0.f, 0.f, 0.f, 0.f, 0.f, 0.f, 0.f};
            if (n < NN) {
                int e0 = g_row[n], e1 = g_row[n + 1];
                __half2 pa[4][4];
                #pragma unroll
                for (int j = 0; j < 4; j++)
                    #pragma unroll
                    for (int k = 0; k < 4; k++)
                        pa[j][k] = __floats2half2_rn(0.f, 0.f);
                int e = e0;
                for (; e + 4 <= e1; e += 4) {
                    #pragma unroll
                    for (int j = 0; j < 4; j++) {
                        int s = __ldg(&g_sorted[e + j]);
                        ushort4 r = __ldg(&pt[s * 8 + fg]);
                        pa[j][0] = __hadd2(pa[j][0], cvt8(r.x));
                        pa[j][1] = __hadd2(pa[j][1], cvt8(r.y));
                        pa[j][2] = __hadd2(pa[j][2], cvt8(r.z));
                        pa[j][3] = __hadd2(pa[j][3], cvt8(r.w));
                    }
                }
                for (; e < e1; e++) {
                    int s = __ldg(&g_sorted[e]);
                    ushort4 r = __ldg(&pt[s * 8 + fg]);
                    pa[0][0] = __hadd2(pa[0][0], cvt8(r.x));
                    pa[0][1] = __hadd2(pa[0][1], cvt8(r.y));
                    pa[0][2] = __hadd2(pa[0][2], cvt8(r.z));
                    pa[0][3] = __hadd2(pa[0][3], cvt8(r.w));
                }
                #pragma unroll
                for (int j = 0; j < 4; j++) {
                    #pragma unroll
                    for (int k = 0; k < 4; k++) {
                        float2 f2 = __half22float2(pa[j][k]);
                        acc[2 * k]     += f2.x;
                        acc[2 * k + 1] += f2.y;
                    }
                }
                // self loop in fp32
                ushort4 rs = pt[n * 8 + fg];
                float2 s0 = __half22float2(cvt8(rs.x));
                float2 s1 = __half22float2(cvt8(rs.y));
                float2 s2 = __half22float2(cvt8(rs.z));
                float2 s3 = __half22float2(cvt8(rs.w));
                acc[0] += s0.x; acc[1] += s0.y; acc[2] += s1.x; acc[3] += s1.y;
                acc[4] += s2.x; acc[5] += s2.y; acc[6] += s3.x; acc[7] += s3.y;
                float sc = g_dinv[n] * P_INV;
                #pragma unroll
                for (int k = 0; k < 8; k++) acc[k] *= sc;
            }
            __half2* hw = (__half2*)&hs[nl * HS_STRIDE + 8 * fg];
            #pragma unroll
            for (int j = 0; j < 4; j++)
                hw[j] = __floats2half2_rn(acc[2 * j], acc[2 * j + 1]);
        }
        __syncthreads();

        // -------- stage B: h2 GEMV for 4 nodes, W2 amortized 4x --------
        float o[4][8];
        #pragma unroll
        for (int i = 0; i < 4; i++)
            #pragma unroll
            for (int j = 0; j < 8; j++) o[i][j] = bloc[j];

        const __half* hp0 = &hs[(rg * 4 + 0) * HS_STRIDE];
        const __half* hp1 = &hs[(rg * 4 + 1) * HS_STRIDE];
        const __half* hp2 = &hs[(rg * 4 + 2) * HS_STRIDE];
        const __half* hp3 = &hs[(rg * 4 + 3) * HS_STRIDE];
        #pragma unroll 4
        for (int k = 0; k < HID; k++) {
            float a0 = __half2float(hp0[k]);
            float a1 = __half2float(hp1[k]);
            float a2 = __half2float(hp2[k]);
            float a3 = __half2float(hp3[k]);
            float4 wA = *(const float4*)&W2s[k * HID + 8 * fg];
            float4 wB = *(const float4*)&W2s[k * HID + 8 * fg + 4];
            o[0][0] = fmaf(a0, wA.x, o[0][0]); o[0][1] = fmaf(a0, wA.y, o[0][1]);
            o[0][2] = fmaf(a0, wA.z, o[0][2]); o[0][3] = fmaf(a0, wA.w, o[0][3]);
            o[0][4] = fmaf(a0, wB.x, o[0][4]); o[0][5] = fmaf(a0, wB.y, o[0][5]);
            o[0][6] = fmaf(a0, wB.z, o[0][6]); o[0][7] = fmaf(a0, wB.w, o[0][7]);
            o[1][0] = fmaf(a1, wA.x, o[1][0]); o[1][1] = fmaf(a1, wA.y, o[1][1]);
            o[1][2] = fmaf(a1, wA.z, o[1][2]); o[1][3] = fmaf(a1, wA.w, o[1][3]);
            o[1][4] = fmaf(a1, wB.x, o[1][4]); o[1][5] = fmaf(a1, wB.y, o[1][5]);
            o[1][6] = fmaf(a1, wB.z, o[1][6]); o[1][7] = fmaf(a1, wB.w, o[1][7]);
            o[2][0] = fmaf(a2, wA.x, o[2][0]); o[2][1] = fmaf(a2, wA.y, o[2][1]);
            o[2][2] = fmaf(a2, wA.z, o[2][2]); o[2][3] = fmaf(a2, wA.w, o[2][3]);
            o[2][4] = fmaf(a2, wB.x, o[2][4]); o[2][5] = fmaf(a2, wB.y, o[2][5]);
            o[2][6] = fmaf(a2, wB.z, o[2][6]); o[2][7] = fmaf(a2, wB.w, o[2][7]);
            o[3][0] = fmaf(a3, wA.x, o[3][0]); o[3][1] = fmaf(a3, wA.y, o[3][1]);
            o[3][2] = fmaf(a3, wA.z, o[3][2]); o[3][3] = fmaf(a3, wA.w, o[3][3]);
            o[3][4] = fmaf(a3, wB.x, o[3][4]); o[3][5] = fmaf(a3, wB.y, o[3][5]);
            o[3][6] = fmaf(a3, wB.z, o[3][6]); o[3][7] = fmaf(a3, wB.w, o[3][7]);
        }
        #pragma unroll
        for (int i = 0; i < 4; i++) {
            int n = tile * TILE2 + rg * 4 + i;
            if (n < NN) {
                #pragma unroll
                for (int j = 0; j < 8; j++)
                    pool8[j] += fmaxf(o[i][j], 0.f);
            }
        }
        __syncthreads();   // hs reused next tile
    }

    // -------- final pool reduction (reuse hs as float scratch) --------
    float* hsf = (float*)hs;   // 32*64 floats = 8 KB <= 16.9 KB
    #pragma unroll
    for (int j = 0; j < 8; j++)
        hsf[rg * HID + 8 * fg + j] = pool8[j];
    __syncthreads();
    if (tid < HID) {
        float s = 0.f;
        #pragma unroll 8
        for (int r = 0; r < 32; r++) s += hsf[r * HID + tid];
        atomicAdd(&g_pool[tid], s);
    }
}

__global__ void k_out(const float* __restrict__ Wfc, const float* __restrict__ bfc,
                      float* __restrict__ out) {
    int t = threadIdx.x;   // 32 threads
    float s = g_pool[t] * Wfc[t] + g_pool[t + 32] * Wfc[t + 32];
    #pragma unroll
    for (int o = 16; o > 0; o >>= 1) s += __shfl_down_sync(0xffffffffu, s, o);
    if (t == 0) out[0] = s * (1.0f / NN) + bfc[0];
}

// ---------------- launch ----------------
extern "C" void kernel_launch(void* const* d_in, const int* in_sizes, int n_in,
                              void* d_out, int out_size) {
    const float2* x2    = (const float2*)d_in[0];
    const void*   edges = d_in[1];
    const float*  W1    = (const float*)d_in[2];
    const float*  b1    = (const float*)d_in[3];
    const float*  W2    = (const float*)d_in[4];
    const float*  b2    = (const float*)d_in[5];
    const float*  Wfc   = (const float*)d_in[6];
    const float*  bfc   = (const float*)d_in[7];
    float* out = (float*)d_out;

    const int T = 256;
    k_detect<<<1, 1>>>((const unsigned long long*)edges);
    k_init<<<(NN + T - 1) / T, T>>>();
    k_count<<<(NE / 4 + T - 1) / T, T>>>(edges);
    k_scan1<<<NBLK1, SCAN_B>>>();
    k_scan2<<<1, 256>>>();
    k_scan3_dinv<<<(NN + T - 1) / T, T>>>(x2);
    k_scatter<<<(NE / 2 + T - 1) / T, T>>>(edges);
    k_h1p<<<(NN * 32 + T - 1) / T, T>>>(W1, b1);
    k_gather2<<<NT2, T>>>(W2, b2);
    k_out<<<1, 32>>>(Wfc, bfc, out);
}

// round 7
// speedup vs baseline: 1.9074x; 1.0111x over previous
#include <cuda_runtime.h>
#include <cuda_fp16.h>
#include <cstdint>

#define NN 100000
#define NE 3200000
#define HID 64
#define SCAN_B 512
#define NBLK1 ((NN + SCAN_B - 1) / SCAN_B)   // 196
#define TILE2 128
#define NT2 ((NN + TILE2 - 1) / TILE2)       // 782
#define HS_STRIDE 66                          // halves; conflict-free staging

// ---------------- scratch (device globals; no allocation) ----------------
__device__ int     g_cnt[NN];
__device__ float   g_dinv[NN];
__device__ float2  g_q[NN];            // q = dinv * x (layer-1 gather table)
__device__ int     g_row[NN + 1];      // CSR row pointers (by dst)
__device__ int     g_slot[NE];         // within-bucket slot per edge
__device__ int     g_sorted[NE];       // src ids sorted by dst
__device__ __half2 g_ph[NN * 32];      // p = dinv*relu(h1), fp16, 128 B/node
__device__ float   g_pool[HID];
__device__ int     g_bsum[NBLK1];
__device__ int     g_flag;             // 1 = edge_index stored as int64

// ---------------- kernels ----------------

// init counters/pool; thread 0 detects int64 vs int32 edge storage.
__global__ void k_init(const unsigned long long* __restrict__ e64) {
    int i = blockIdx.x * blockDim.x + threadIdx.x;
    if (i < NN) g_cnt[i] = 0;
    if (i < HID) g_pool[i] = 0.0f;
    if (i == 0) {
        int is64 = 1;
        #pragma unroll
        for (int k = 0; k < 8; k++)
            if (e64[k] >= (unsigned long long)NN) { is64 = 0; break; }
        g_flag = is64;
    }
}

// Histogram dst AND record each edge's slot within its bucket. 4 edges/thread.
__global__ void k_count(const void* __restrict__ edges) {
    int e0 = (blockIdx.x * blockDim.x + threadIdx.x) * 4;
    if (e0 >= NE) return;
    int d[4];
    if (g_flag) {
        const longlong2* d2 = (const longlong2*)((const long long*)edges + NE);
        longlong2 a = d2[e0 >> 1], b = d2[(e0 >> 1) + 1];
        d[0] = (int)a.x; d[1] = (int)a.y; d[2] = (int)b.x; d[3] = (int)b.y;
    } else {
        const int4* d4 = (const int4*)((const int*)edges + NE);
        int4 a = d4[e0 >> 2];
        d[0] = a.x; d[1] = a.y; d[2] = a.z; d[3] = a.w;
    }
    int sl[4];
    #pragma unroll
    for (int j = 0; j < 4; j++) sl[j] = atomicAdd(&g_cnt[d[j]], 1);
    *(int4*)&g_slot[e0] = make_int4(sl[0], sl[1], sl[2], sl[3]);
}

// --- shfl-based exclusive scan of g_cnt -> g_row ---
__global__ void k_scan1() {
    __shared__ int wsum[16];
    int t = threadIdx.x, i = blockIdx.x * SCAN_B + t;
    int lane = t & 31, w = t >> 5;
    int v = (i < NN) ? g_cnt[i] : 0;
    int s = v;
    #pragma unroll
    for (int o = 1; o < 32; o <<= 1) {
        int u = __shfl_up_sync(0xffffffffu, s, o);
        if (lane >= o) s += u;
    }
    if (lane == 31) wsum[w] = s;
    __syncthreads();
    if (w == 0) {
        int ws = (lane < 16) ? wsum[lane] : 0;
        #pragma unroll
        for (int o = 1; o < 16; o <<= 1) {
            int u = __shfl_up_sync(0xffffffffu, ws, o);
            if (lane >= o) ws += u;
        }
        if (lane < 16) wsum[lane] = ws;
    }
    __syncthreads();
    int base = (w > 0) ? wsum[w - 1] : 0;
    int incl = s + base;
    if (i < NN) g_row[i] = incl - v;
    if (t == SCAN_B - 1) g_bsum[blockIdx.x] = incl;
}

__global__ void k_scan2() {
    __shared__ int wsum[8];
    int t = threadIdx.x;
    int lane = t & 31, w = t >> 5;
    int v = (t < NBLK1) ? g_bsum[t] : 0;
    int s = v;
    #pragma unroll
    for (int o = 1; o < 32; o <<= 1) {
        int u = __shfl_up_sync(0xffffffffu, s, o);
        if (lane >= o) s += u;
    }
    if (lane == 31) wsum[w] = s;
    __syncthreads();
    if (w == 0) {
        int ws = (lane < 8) ? wsum[lane] : 0;
        #pragma unroll
        for (int o = 1; o < 8; o <<= 1) {
            int u = __shfl_up_sync(0xffffffffu, ws, o);
            if (lane >= o) ws += u;
        }
        if (lane < 8) wsum[lane] = ws;
    }
    __syncthreads();
    int base = (w > 0) ? wsum[w - 1] : 0;
    if (t < NBLK1) g_bsum[t] = s + base - v;
}

__global__ void k_scan3_dinv(const float2* __restrict__ x2) {
    int i = blockIdx.x * blockDim.x + threadIdx.x;
    if (i < NN) {
        int r = g_row[i] + g_bsum[i / SCAN_B];
        g_row[i] = r;
        float d = rsqrtf((float)g_cnt[i] + 1.0f);
        g_dinv[i] = d;
        float2 xv = x2[i];
        g_q[i] = make_float2(xv.x * d, xv.y * d);
    }
    if (i == 0) g_row[NN] = NE;
}

// Atomic-free counting-sort scatter: addr = row[dst] + slot[e]. 4 edges/thread.
__global__ void k_scatter(const void* __restrict__ edges) {
    int e0 = (blockIdx.x * blockDim.x + threadIdx.x) * 4;
    if (e0 >= NE) return;
    int s[4], d[4];
    if (g_flag) {
        const longlong2* sp = (const longlong2*)edges;
        const longlong2* dp = (const longlong2*)((const long long*)edges + NE);
        longlong2 sa = sp[e0 >> 1], sb = sp[(e0 >> 1) + 1];
        longlong2 da = dp[e0 >> 1], db = dp[(e0 >> 1) + 1];
        s[0] = (int)sa.x; s[1] = (int)sa.y; s[2] = (int)sb.x; s[3] = (int)sb.y;
        d[0] = (int)da.x; d[1] = (int)da.y; d[2] = (int)db.x; d[3] = (int)db.y;
    } else {
        const int4* sp = (const int4*)edges;
        const int4* dp = (const int4*)((const int*)edges + NE);
        int4 sa = sp[e0 >> 2], da = dp[e0 >> 2];
        s[0] = sa.x; s[1] = sa.y; s[2] = sa.z; s[3] = sa.w;
        d[0] = da.x; d[1] = da.y; d[2] = da.z; d[3] = da.w;
    }
    int4 sl = *(const int4*)&g_slot[e0];
    g_sorted[__ldg(&g_row[d[0]]) + sl.x] = s[0];
    g_sorted[__ldg(&g_row[d[1]]) + sl.y] = s[1];
    g_sorted[__ldg(&g_row[d[2]]) + sl.z] = s[2];
    g_sorted[__ldg(&g_row[d[3]]) + sl.w] = s[3];
}

// Warp-per-node: layer-1 CSR gather of q + 2->64 GEMV + relu -> fp16 p row.
__global__ void __launch_bounds__(256) k_h1p(const float* __restrict__ W1,
                                             const float* __restrict__ b1) {
    int gt = blockIdx.x * blockDim.x + threadIdx.x;
    int n = gt >> 5;
    if (n >= NN) return;
    int lane = gt & 31;

    int e0 = g_row[n], e1 = g_row[n + 1];
    float ax = 0.f, ay = 0.f;
    for (int e = e0 + lane; e < e1; e += 32) {
        float2 q = __ldg(&g_q[g_sorted[e]]);
        ax += q.x; ay += q.y;
    }
    #pragma unroll
    for (int o = 16; o > 0; o >>= 1) {
        ax += __shfl_xor_sync(0xffffffffu, ax, o);
        ay += __shfl_xor_sync(0xffffffffu, ay, o);
    }
    float2 qn = g_q[n];
    float dv = g_dinv[n];
    float xax = (ax + qn.x) * dv;
    float xay = (ay + qn.y) * dv;

    int f = 2 * lane;
    float v0 = fmaf(xax, __ldg(&W1[f]),     fmaf(xay, __ldg(&W1[HID + f]),     __ldg(&b1[f])));
    float v1 = fmaf(xax, __ldg(&W1[f + 1]), fmaf(xay, __ldg(&W1[HID + f + 1]), __ldg(&b1[f + 1])));
    v0 = fmaxf(v0, 0.0f) * dv;
    v1 = fmaxf(v1, 0.0f) * dv;
    g_ph[n * 32 + lane] = __floats2half2_rn(v0, v1);
}

// Fused: fp16 CSR gather (layer-2 agg) + node-batched h2 GEMV + relu + pool.
// 256 threads: fg = tid&7 (8 feats), rg = tid>>3; thread handles nodes rg*4+i.
__global__ void __launch_bounds__(256) k_gather2(const float* __restrict__ W2,
                                                 const float* __restrict__ b2) {
    __shared__ float  W2s[HID * HID];             // 16 KB, [k*64 + f]
    __shared__ __half hs[TILE2 * HS_STRIDE];      // 16.9 KB

    int tid = threadIdx.x;
    int fg = tid & 7, rg = tid >> 3;

    for (int i = tid; i < HID * HID; i += 256) W2s[i] = W2[i];
    float bloc[8];
    #pragma unroll
    for (int j = 0; j < 8; j++) bloc[j] = __ldg(&b2[8 * fg + j]);
    __syncthreads();

    float pool8[8] = {0.f, 0.f, 0.f, 0.f, 0.f, 0.f, 0.f, 0.f};
    const uint4* pt = (const uint4*)g_ph;    // 8 half2 per row-quarter; uint4 = 4 half2

    for (int tile = blockIdx.x; tile < NT2; tile += gridDim.x) {
        // -------- stage A: gather agg for 4 nodes, write fp16 to hs --------
        #pragma unroll
        for (int i = 0; i < 4; i++) {
            int nl = rg * 4 + i;
            int n = tile * TILE2 + nl;
            float acc[8] = {0.f, 0.f, 0.f, 0.f, 0.f, 0.f, 0.f, 0.f};
            if (n < NN) {
                int e0 = g_row[n], e1 = g_row[n + 1];
                __half2 pa[4][4];
                #pragma unroll
                for (int j = 0; j < 4; j++)
                    #pragma unroll
                    for (int k = 0; k < 4; k++)
                        pa[j][k] = __floats2half2_rn(0.f, 0.f);
                int e = e0;
                for (; e + 4 <= e1; e += 4) {
                    #pragma unroll
                    for (int j = 0; j < 4; j++) {
                        int s = __ldg(&g_sorted[e + j]);
                        uint4 r = __ldg(&pt[s * 8 + fg]);
                        pa[j][0] = __hadd2(pa[j][0], *(__half2*)&r.x);
                        pa[j][1] = __hadd2(pa[j][1], *(__half2*)&r.y);
                        pa[j][2] = __hadd2(pa[j][2], *(__half2*)&r.z);
                        pa[j][3] = __hadd2(pa[j][3], *(__half2*)&r.w);
                    }
                }
                for (; e < e1; e++) {
                    int s = __ldg(&g_sorted[e]);
                    uint4 r = __ldg(&pt[s * 8 + fg]);
                    pa[0][0] = __hadd2(pa[0][0], *(__half2*)&r.x);
                    pa[0][1] = __hadd2(pa[0][1], *(__half2*)&r.y);
                    pa[0][2] = __hadd2(pa[0][2], *(__half2*)&r.z);
                    pa[0][3] = __hadd2(pa[0][3], *(__half2*)&r.w);
                }
                #pragma unroll
                for (int j = 0; j < 4; j++) {
                    #pragma unroll
                    for (int k = 0; k < 4; k++) {
                        float2 f2 = __half22float2(pa[j][k]);
                        acc[2 * k]     += f2.x;
                        acc[2 * k + 1] += f2.y;
                    }
                }
                // self loop in fp32
                uint4 rs = pt[n * 8 + fg];
                float2 s0 = __half22float2(*(__half2*)&rs.x);
                float2 s1 = __half22float2(*(__half2*)&rs.y);
                float2 s2 = __half22float2(*(__half2*)&rs.z);
                float2 s3 = __half22float2(*(__half2*)&rs.w);
                acc[0] += s0.x; acc[1] += s0.y; acc[2] += s1.x; acc[3] += s1.y;
                acc[4] += s2.x; acc[5] += s2.y; acc[6] += s3.x; acc[7] += s3.y;
                float sc = g_dinv[n];
                #pragma unroll
                for (int k = 0; k < 8; k++) acc[k] *= sc;
            }
            __half2* hw = (__half2*)&hs[nl * HS_STRIDE + 8 * fg];
            #pragma unroll
            for (int j = 0; j < 4; j++)
                hw[j] = __floats2half2_rn(acc[2 * j], acc[2 * j + 1]);
        }
        __syncthreads();

        // -------- stage B: h2 GEMV for 4 nodes, W2 amortized 4x --------
        float o[4][8];
        #pragma unroll
        for (int i = 0; i < 4; i++)
            #pragma unroll
            for (int j = 0; j < 8; j++) o[i][j] = bloc[j];

        const __half* hp0 = &hs[(rg * 4 + 0) * HS_STRIDE];
        const __half* hp1 = &hs[(rg * 4 + 1) * HS_STRIDE];
        const __half* hp2 = &hs[(rg * 4 + 2) * HS_STRIDE];
        const __half* hp3 = &hs[(rg * 4 + 3) * HS_STRIDE];
        #pragma unroll 4
        for (int k = 0; k < HID; k++) {
            float a0 = __half2float(hp0[k]);
            float a1 = __half2float(hp1[k]);
            float a2 = __half2float(hp2[k]);
            float a3 = __half2float(hp3[k]);
            float4 wA = *(const float4*)&W2s[k * HID + 8 * fg];
            float4 wB = *(const float4*)&W2s[k * HID + 8 * fg + 4];
            o[0][0] = fmaf(a0, wA.x, o[0][0]); o[0][1] = fmaf(a0, wA.y, o[0][1]);
            o[0][2] = fmaf(a0, wA.z, o[0][2]); o[0][3] = fmaf(a0, wA.w, o[0][3]);
            o[0][4] = fmaf(a0, wB.x, o[0][4]); o[0][5] = fmaf(a0, wB.y, o[0][5]);
            o[0][6] = fmaf(a0, wB.z, o[0][6]); o[0][7] = fmaf(a0, wB.w, o[0][7]);
            o[1][0] = fmaf(a1, wA.x, o[1][0]); o[1][1] = fmaf(a1, wA.y, o[1][1]);
            o[1][2] = fmaf(a1, wA.z, o[1][2]); o[1][3] = fmaf(a1, wA.w, o[1][3]);
            o[1][4] = fmaf(a1, wB.x, o[1][4]); o[1][5] = fmaf(a1, wB.y, o[1][5]);
            o[1][6] = fmaf(a1, wB.z, o[1][6]); o[1][7] = fmaf(a1, wB.w, o[1][7]);
            o[2][0] = fmaf(a2, wA.x, o[2][0]); o[2][1] = fmaf(a2, wA.y, o[2][1]);
            o[2][2] = fmaf(a2, wA.z, o[2][2]); o[2][3] = fmaf(a2, wA.w, o[2][3]);
            o[2][4] = fmaf(a2, wB.x, o[2][4]); o[2][5] = fmaf(a2, wB.y, o[2][5]);
            o[2][6] = fmaf(a2, wB.z, o[2][6]); o[2][7] = fmaf(a2, wB.w, o[2][7]);
            o[3][0] = fmaf(a3, wA.x, o[3][0]); o[3][1] = fmaf(a3, wA.y, o[3][1]);
            o[3][2] = fmaf(a3, wA.z, o[3][2]); o[3][3] = fmaf(a3, wA.w, o[3][3]);
            o[3][4] = fmaf(a3, wB.x, o[3][4]); o[3][5] = fmaf(a3, wB.y, o[3][5]);
            o[3][6] = fmaf(a3, wB.z, o[3][6]); o[3][7] = fmaf(a3, wB.w, o[3][7]);
        }
        #pragma unroll
        for (int i = 0; i < 4; i++) {
            int n = tile * TILE2 + rg * 4 + i;
            if (n < NN) {
                #pragma unroll
                for (int j = 0; j < 8; j++)
                    pool8[j] += fmaxf(o[i][j], 0.f);
            }
        }
        __syncthreads();   // hs reused next tile
    }

    // -------- final pool reduction (reuse hs as float scratch) --------
    float* hsf = (float*)hs;   // 32*64 floats = 8 KB
    #pragma unroll
    for (int j = 0; j < 8; j++)
        hsf[rg * HID + 8 * fg + j] = pool8[j];
    __syncthreads();
    if (tid < HID) {
        float s = 0.f;
        #pragma unroll 8
        for (int r = 0; r < 32; r++) s += hsf[r * HID + tid];
        atomicAdd(&g_pool[tid], s);
    }
}

__global__ void k_out(const float* __restrict__ Wfc, const float* __restrict__ bfc,
                      float* __restrict__ out) {
    int t = threadIdx.x;   // 32 threads
    float s = g_pool[t] * Wfc[t] + g_pool[t + 32] * Wfc[t + 32];
    #pragma unroll
    for (int o = 16; o > 0; o >>= 1) s += __shfl_down_sync(0xffffffffu, s, o);
    if (t == 0) out[0] = s * (1.0f / NN) + bfc[0];
}

// ---------------- launch ----------------
extern "C" void kernel_launch(void* const* d_in, const int* in_sizes, int n_in,
                              void* d_out, int out_size) {
    const float2* x2    = (const float2*)d_in[0];
    const void*   edges = d_in[1];
    const float*  W1    = (const float*)d_in[2];
    const float*  b1    = (const float*)d_in[3];
    const float*  W2    = (const float*)d_in[4];
    const float*  b2    = (const float*)d_in[5];
    const float*  Wfc   = (const float*)d_in[6];
    const float*  bfc   = (const float*)d_in[7];
    float* out = (float*)d_out;

    const int T = 256;
    k_init<<<(NN + T - 1) / T, T>>>((const unsigned long long*)edges);
    k_count<<<(NE / 4 + T - 1) / T, T>>>(edges);
    k_scan1<<<NBLK1, SCAN_B>>>();
    k_scan2<<<1, 256>>>();
    k_scan3_dinv<<<(NN + T - 1) / T, T>>>(x2);
    k_scatter<<<(NE / 4 + T - 1) / T, T>>>(edges);
    k_h1p<<<(NN * 32 + T - 1) / T, T>>>(W1, b1);
    k_gather2<<<NT2, T>>>(W2, b2);
    k_out<<<1, 32>>>(Wfc, bfc, out);
}